// round 13
// baseline (speedup 1.0000x reference)
#include <cuda_runtime.h>

#define SEQ       128
#define BATCH     512
#define INPUT_DIM 128
#define HIDDEN    128
#define NQ        8

typedef unsigned long long u64;

__device__ __forceinline__ u64 pk(float lo, float hi) {
    u64 r; asm("mov.b64 %0, {%1, %2};" : "=l"(r) : "f"(lo), "f"(hi)); return r;
}
__device__ __forceinline__ void upk(u64 v, float& lo, float& hi) {
    asm("mov.b64 {%0, %1}, %2;" : "=f"(lo), "=f"(hi) : "l"(v));
}
#define FMA2(o,a,b,c) asm("fma.rn.f32x2 %0, %1, %2, %3;" : "=l"(o) : "l"(a), "l"(b), "l"(c))

// Precomputed x-part of q_in (+ bias): [SEQ*BATCH, 8]  (2MB device scratch)
__device__ float g_qx[SEQ * BATCH * NQ];

// ---------------- pre-kernel: g_qx[tb][r] = Wq[r, :128] . x[tb] + bq[r] ----------------
__global__ __launch_bounds__(128, 8)
void qx_pre(const float* __restrict__ inputs, const float* __restrict__ Wq,
            const float* __restrict__ bq)
{
    __shared__ float4 sW[8][32];   // x-part of rows 0..7
    const int tid = threadIdx.x, wid = tid >> 5, lane = tid & 31;
    const float4* Wq4 = (const float4*)Wq;
    for (int i = tid; i < 256; i += 128) sW[i >> 5][i & 31] = Wq4[(i >> 5) * 64 + (i & 31)];
    __syncthreads();

    int base = blockIdx.x * 16 + wid * 4;
    #pragma unroll
    for (int k = 0; k < 4; k++) {
        int tb = base + k;
        float4 xv = ((const float4*)(inputs + (size_t)tb * INPUT_DIM))[lane];
        float acc[8];
        #pragma unroll
        for (int r = 0; r < 8; r++) {
            float4 w = sW[r][lane];
            float a = xv.x * w.x;
            a = fmaf(xv.y, w.y, a); a = fmaf(xv.z, w.z, a); a = fmaf(xv.w, w.w, a);
            acc[r] = a;
        }
        const unsigned FM = 0xffffffffu;
        int t0 = lane & 1;
        float s0 = t0 ? acc[0] : acc[1], s1 = t0 ? acc[2] : acc[3];
        float s2 = t0 ? acc[4] : acc[5], s3 = t0 ? acc[6] : acc[7];
        float r0 = __shfl_xor_sync(FM, s0, 1);
        float r1 = __shfl_xor_sync(FM, s1, 1);
        float r2 = __shfl_xor_sync(FM, s2, 1);
        float r3 = __shfl_xor_sync(FM, s3, 1);
        float w0_ = (t0 ? acc[1] : acc[0]) + r0;
        float w1_ = (t0 ? acc[3] : acc[2]) + r1;
        float w2_ = (t0 ? acc[5] : acc[4]) + r2;
        float w3_ = (t0 ? acc[7] : acc[6]) + r3;
        int t1 = (lane >> 1) & 1;
        float s4 = t1 ? w0_ : w1_, s5 = t1 ? w2_ : w3_;
        float r4 = __shfl_xor_sync(FM, s4, 2);
        float r5 = __shfl_xor_sync(FM, s5, 2);
        float x0_ = (t1 ? w1_ : w0_) + r4;
        float x1_ = (t1 ? w3_ : w2_) + r5;
        int t2 = (lane >> 2) & 1;
        float s6 = t2 ? x0_ : x1_;
        float r6 = __shfl_xor_sync(FM, s6, 4);
        float y = (t2 ? x1_ : x0_) + r6;
        y += __shfl_xor_sync(FM, y, 8);
        y += __shfl_xor_sync(FM, y, 16);
        if (lane < 8) g_qx[tb * NQ + lane] = y + bq[lane];
    }
}

// ------------- recurrent kernel: 4 warps/block, redundant DP + split epilogue -------------
__global__ __launch_bounds__(128, 4)
void qlstm_all(const float* __restrict__ Wq,
               const float* __restrict__ pf,
               const float* __restrict__ pi_,
               const float* __restrict__ pg,
               const float* __restrict__ po,
               const float* __restrict__ Wf, const float* __restrict__ bf,
               const float* __restrict__ Wi, const float* __restrict__ bi,
               const float* __restrict__ Wg, const float* __restrict__ bg,
               const float* __restrict__ Wo, const float* __restrict__ bo,
               float* __restrict__ out)
{
    const int b    = blockIdx.x;
    const int tid  = threadIdx.x;
    const int wid  = tid >> 5;
    const int lane = tid & 31;
    const int g    = lane >> 3;      // gate 0..3 (f,i,g,o)
    const int v    = lane & 7;       // output wire for the DP
    const unsigned FM = 0xffffffffu;

    __shared__ float4 sWqH[8][32];              // 4KB : Wq rows 0..7, h-part
    __shared__ float4 sWg4[NQ][HIDDEN];         // 16KB: (Wf,Wi,Wg,Wo) per (wire,hidden)
    __shared__ float  sH[2][HIDDEN];            // double-buffered h
    __shared__ __align__(16) float zsm[4][NQ][4];  // per-WARP private [wire][gate]

    // ---- per-lane circuit constants (lane's gate), FULL angles ----
    float Cg[NQ], Sg[NQ], cg[NQ], sg[NQ];
    {
        const float* prm = (g == 0) ? pf : (g == 1) ? pi_ : (g == 2) ? pg : po;
        #pragma unroll
        for (int w = 0; w < NQ; w++) {
            __sincosf(prm[w],      &Sg[w], &Cg[w]);   // d0 layer
            __sincosf(prm[NQ + w], &sg[w], &cg[w]);   // d1 layer
        }
    }
    // ---- weights to smem ----
    {
        const float4* Wq4 = (const float4*)Wq;
        for (int i = tid; i < 256; i += 128)
            sWqH[i >> 5][i & 31] = Wq4[(i >> 5) * 64 + 32 + (i & 31)];
        for (int i = tid; i < HIDDEN * NQ; i += 128) {
            int h = i >> 3, w = i & 7;
            sWg4[w][h] = make_float4(Wf[i], Wi[i], Wg[i], Wo[i]);
        }
        sH[0][tid] = 0.f;
    }

    // epilogue: this thread owns hidden unit h = wid*32 + lane
    const int hu = wid * 32 + lane;
    const float bfr = bf[hu], bir = bi[hu], bgr = bg[hu], bor = bo[hu];
    float creg = 0.f, hn = 0.f;

    float qxc = g_qx[(size_t)b * NQ + v];    // t=0, row v (dup across g)
    __syncthreads();

    for (int t = 0; t < SEQ; t++) {
        const int buf = t & 1;
        __syncthreads();   // ONE barrier per step: h[buf] visible

        // ---- h-GEMM: all 8 rows, 9-shfl multi-reduce (redundant in all warps) ----
        float4 hv = ((const float4*)sH[buf])[lane];
        float acc[8];
        #pragma unroll
        for (int r = 0; r < 8; r++) {
            float4 w = sWqH[r][lane];
            float a = hv.x * w.x;
            a = fmaf(hv.y, w.y, a); a = fmaf(hv.z, w.z, a); a = fmaf(hv.w, w.w, a);
            acc[r] = a;
        }
        float y;
        {
            int t0 = lane & 1;
            float s0 = t0 ? acc[0] : acc[1], s1 = t0 ? acc[2] : acc[3];
            float s2 = t0 ? acc[4] : acc[5], s3 = t0 ? acc[6] : acc[7];
            float r0 = __shfl_xor_sync(FM, s0, 1);
            float r1 = __shfl_xor_sync(FM, s1, 1);
            float r2 = __shfl_xor_sync(FM, s2, 1);
            float r3 = __shfl_xor_sync(FM, s3, 1);
            float w0_ = (t0 ? acc[1] : acc[0]) + r0;
            float w1_ = (t0 ? acc[3] : acc[2]) + r1;
            float w2_ = (t0 ? acc[5] : acc[4]) + r2;
            float w3_ = (t0 ? acc[7] : acc[6]) + r3;
            int t1 = (lane >> 1) & 1;
            float s4 = t1 ? w0_ : w1_, s5 = t1 ? w2_ : w3_;
            float r4 = __shfl_xor_sync(FM, s4, 2);
            float r5 = __shfl_xor_sync(FM, s5, 2);
            float x0_ = (t1 ? w1_ : w0_) + r4;
            float x1_ = (t1 ? w3_ : w2_) + r5;
            int t2 = (lane >> 2) & 1;
            float s6 = t2 ? x0_ : x1_;
            float r6 = __shfl_xor_sync(FM, s6, 4);
            y = (t2 ? x1_ : x0_) + r6;
            y += __shfl_xor_sync(FM, y, 8);
            y += __shfl_xor_sync(FM, y, 16);   // row (lane&7) total, ALL lanes
        }
        // prefetch next qx (h-independent)
        float qxn = 0.f;
        if (t + 1 < SEQ) qxn = g_qx[((size_t)(t + 1) * BATCH + b) * NQ + v];

        float sq, cq;
        __sincosf(y + qxc, &sq, &cq);        // cs of wire j lives in lanes with v=j

        // ---- Heisenberg DP (real 4-state): lane -> z[g][v] ----
        float a_ = 1.f, bb = 0.f, c_ = 0.f, d_ = 0.f;
        #pragma unroll
        for (int j = 7; j >= 0; j--) {
            float zf, xf, yf;
            if (j == 7) { zf = 0.f; xf = 1.f; yf = 0.f; }
            else {
                float cqj = __shfl_sync(FM, cq, j + 1);
                float sqj = __shfl_sync(FM, sq, j + 1);
                zf = Cg[j + 1] * cqj;
                xf = Sg[j + 1] * cqj;
                yf = -sqj;
            }
            if (j <= v) {
                float cj = cg[j], sj = sg[j];
                float na = cj * fmaf(yf, d_, bb * zf);
                float nb = cj * fmaf(xf, c_, a_);
                float nc = -sj * fmaf(xf, a_, c_);
                float nd = -sj * fmaf(-yf, bb, d_ * zf);
                a_ = na; bb = nb; c_ = nc; d_ = nd;
            }
        }
        {
            float cq0 = __shfl_sync(FM, cq, 0);
            float sq0 = __shfl_sync(FM, sq, 0);
            float E = a_;
            E = fmaf(Sg[0] * cq0, c_, E);
            E = fmaf(Cg[0] * cq0, bb, E);
            E = fmaf(-sq0, d_, E);
            zsm[wid][v][g] = E;              // warp-private copy
        }
        __syncwarp();

        // ---- epilogue: ONE hidden unit per thread (unit hu) ----
        {
            u64 accfi = pk(bfr, bir);
            u64 accgo = pk(bgr, bor);
            #pragma unroll
            for (int w = 0; w < NQ; w++) {
                float4 zz = *(const float4*)&zsm[wid][w][0];   // broadcast
                float4 ww = sWg4[w][hu];
                FMA2(accfi, pk(zz.x, zz.y), pk(ww.x, ww.y), accfi);
                FMA2(accgo, pk(zz.z, zz.w), pk(ww.z, ww.w), accgo);
            }
            float accf, acci, accg, acco;
            upk(accfi, accf, acci);
            upk(accgo, accg, acco);

            float fg = __fdividef(1.f, 1.f + __expf(-accf));
            float ig = __fdividef(1.f, 1.f + __expf(-acci));
            float e2 = __expf(2.f * accg);
            float gg = __fdividef(e2 - 1.f, e2 + 1.f);
            float og = __fdividef(1.f, 1.f + __expf(-acco));

            creg = fmaf(fg, creg, ig * gg);
            float e2c = __expf(2.f * creg);
            hn = og * __fdividef(e2c - 1.f, e2c + 1.f);

            sH[buf ^ 1][hu] = hn;            // next step's h (guarded by loop-top barrier)
            out[(size_t)t * BATCH * HIDDEN + (size_t)b * HIDDEN + hu] = hn;
        }
        qxc = qxn;
    }

    // ---- final hx, cx ----
    size_t base = (size_t)SEQ * BATCH * HIDDEN;
    out[base + (size_t)b * HIDDEN + hu] = hn;
    out[base + (size_t)BATCH * HIDDEN + (size_t)b * HIDDEN + hu] = creg;
}

extern "C" void kernel_launch(void* const* d_in, const int* in_sizes, int n_in,
                              void* d_out, int out_size)
{
    const float* inputs = (const float*)d_in[0];
    const float* Wq     = (const float*)d_in[1];
    const float* bq     = (const float*)d_in[2];
    const float* pf     = (const float*)d_in[3];
    const float* pi_    = (const float*)d_in[4];
    const float* pg     = (const float*)d_in[5];
    const float* po     = (const float*)d_in[6];
    const float* Wf     = (const float*)d_in[7];
    const float* bf     = (const float*)d_in[8];
    const float* Wi     = (const float*)d_in[9];
    const float* bi     = (const float*)d_in[10];
    const float* Wg     = (const float*)d_in[11];
    const float* bg     = (const float*)d_in[12];
    const float* Wo     = (const float*)d_in[13];
    const float* bo     = (const float*)d_in[14];
    float* out = (float*)d_out;

    qx_pre<<<4096, 128>>>(inputs, Wq, bq);
    qlstm_all<<<BATCH, 128>>>(Wq, pf, pi_, pg, po,
                              Wf, bf, Wi, bi, Wg, bg, Wo, bo, out);
}

// round 14
// speedup vs baseline: 1.2950x; 1.2950x over previous
#include <cuda_runtime.h>

#define SEQ       128
#define BATCH     512
#define INPUT_DIM 128
#define HIDDEN    128
#define NQ        8

typedef unsigned long long u64;

__device__ __forceinline__ u64 pk(float lo, float hi) {
    u64 r; asm("mov.b64 %0, {%1, %2};" : "=l"(r) : "f"(lo), "f"(hi)); return r;
}
__device__ __forceinline__ void upk(u64 v, float& lo, float& hi) {
    asm("mov.b64 {%0, %1}, %2;" : "=f"(lo), "=f"(hi) : "l"(v));
}
#define FMA2(o,a,b,c) asm("fma.rn.f32x2 %0, %1, %2, %3;" : "=l"(o) : "l"(a), "l"(b), "l"(c))

// Precomputed x-part of q_in (+ bias): [SEQ*BATCH, 8]  (2MB device scratch)
__device__ float g_qx[SEQ * BATCH * NQ];

// ---------------- pre-kernel: g_qx[tb][r] = Wq[r, :128] . x[tb] + bq[r] ----------------
__global__ __launch_bounds__(128, 8)
void qx_pre(const float* __restrict__ inputs, const float* __restrict__ Wq,
            const float* __restrict__ bq)
{
    __shared__ float4 sW[8][32];   // x-part of rows 0..7
    const int tid = threadIdx.x, wid = tid >> 5, lane = tid & 31;
    const float4* Wq4 = (const float4*)Wq;
    for (int i = tid; i < 256; i += 128) sW[i >> 5][i & 31] = Wq4[(i >> 5) * 64 + (i & 31)];
    __syncthreads();

    int base = blockIdx.x * 16 + wid * 4;
    #pragma unroll
    for (int k = 0; k < 4; k++) {
        int tb = base + k;
        float4 xv = ((const float4*)(inputs + (size_t)tb * INPUT_DIM))[lane];
        float acc[8];
        #pragma unroll
        for (int r = 0; r < 8; r++) {
            float4 w = sW[r][lane];
            float a = xv.x * w.x;
            a = fmaf(xv.y, w.y, a); a = fmaf(xv.z, w.z, a); a = fmaf(xv.w, w.w, a);
            acc[r] = a;
        }
        const unsigned FM = 0xffffffffu;
        int t0 = lane & 1;
        float s0 = t0 ? acc[0] : acc[1], s1 = t0 ? acc[2] : acc[3];
        float s2 = t0 ? acc[4] : acc[5], s3 = t0 ? acc[6] : acc[7];
        float r0 = __shfl_xor_sync(FM, s0, 1);
        float r1 = __shfl_xor_sync(FM, s1, 1);
        float r2 = __shfl_xor_sync(FM, s2, 1);
        float r3 = __shfl_xor_sync(FM, s3, 1);
        float w0_ = (t0 ? acc[1] : acc[0]) + r0;
        float w1_ = (t0 ? acc[3] : acc[2]) + r1;
        float w2_ = (t0 ? acc[5] : acc[4]) + r2;
        float w3_ = (t0 ? acc[7] : acc[6]) + r3;
        int t1 = (lane >> 1) & 1;
        float s4 = t1 ? w0_ : w1_, s5 = t1 ? w2_ : w3_;
        float r4 = __shfl_xor_sync(FM, s4, 2);
        float r5 = __shfl_xor_sync(FM, s5, 2);
        float x0_ = (t1 ? w1_ : w0_) + r4;
        float x1_ = (t1 ? w3_ : w2_) + r5;
        int t2 = (lane >> 2) & 1;
        float s6 = t2 ? x0_ : x1_;
        float r6 = __shfl_xor_sync(FM, s6, 4);
        float y = (t2 ? x1_ : x0_) + r6;
        y += __shfl_xor_sync(FM, y, 8);
        y += __shfl_xor_sync(FM, y, 16);
        if (lane < 8) g_qx[tb * NQ + lane] = y + bq[lane];
    }
}

// ------ recurrent kernel: 4 INDEPENDENT warps/block (warp w <-> batch 4*bid+w) ------
// No block barriers in the loop; warps spread across all 4 SMSPs.
__global__ __launch_bounds__(128)
void qlstm_all(const float* __restrict__ Wq,
               const float* __restrict__ pf,
               const float* __restrict__ pi_,
               const float* __restrict__ pg,
               const float* __restrict__ po,
               const float* __restrict__ Wf, const float* __restrict__ bf,
               const float* __restrict__ Wi, const float* __restrict__ bi,
               const float* __restrict__ Wg, const float* __restrict__ bg,
               const float* __restrict__ Wo, const float* __restrict__ bo,
               float* __restrict__ out)
{
    const int tid  = threadIdx.x;
    const int wid  = tid >> 5;
    const int lane = tid & 31;
    const int b    = blockIdx.x * 4 + wid;   // this warp's batch element
    const int g    = lane >> 3;              // gate 0..3 (f,i,g,o)
    const int v    = lane & 7;               // output wire for the DP
    const unsigned FM = 0xffffffffu;

    __shared__ float4 sWqH[8][32];               // 4KB : Wq rows 0..7, h-part (shared)
    __shared__ float4 sWg4[NQ][HIDDEN];          // 16KB: (Wf,Wi,Wg,Wo) (shared)
    __shared__ float  sH[4][HIDDEN];             // per-warp h
    __shared__ __align__(16) float zsm[4][NQ][4];// per-warp [wire][gate]

    // ---- per-lane circuit constants (lane's gate), FULL angles ----
    float Cg[NQ], Sg[NQ], cg[NQ], sg[NQ];
    {
        const float* prm = (g == 0) ? pf : (g == 1) ? pi_ : (g == 2) ? pg : po;
        #pragma unroll
        for (int w = 0; w < NQ; w++) {
            __sincosf(prm[w],      &Sg[w], &Cg[w]);   // d0 layer
            __sincosf(prm[NQ + w], &sg[w], &cg[w]);   // d1 layer
        }
    }
    // ---- weights to smem (cooperative, once) ----
    {
        const float4* Wq4 = (const float4*)Wq;
        for (int i = tid; i < 256; i += 128)
            sWqH[i >> 5][i & 31] = Wq4[(i >> 5) * 64 + 32 + (i & 31)];
        for (int i = tid; i < HIDDEN * NQ; i += 128) {
            int h = i >> 3, w = i & 7;
            sWg4[w][h] = make_float4(Wf[i], Wi[i], Wg[i], Wo[i]);
        }
        ((float4*)sH[wid])[lane] = make_float4(0.f, 0.f, 0.f, 0.f);
    }
    // per-lane biases for its 4 hidden units h = u*32+lane
    float bfv[4], biv[4], bgv[4], bov[4], cv[4];
    #pragma unroll
    for (int u = 0; u < 4; u++) {
        int h = u * 32 + lane;
        bfv[u] = bf[h]; biv[u] = bi[h]; bgv[u] = bg[h]; bov[u] = bo[h];
        cv[u] = 0.f;
    }

    float qxc = g_qx[(size_t)b * NQ + v];    // t=0, row v
    float hn[4];
    __syncthreads();   // weights + sH init visible (ONLY block barrier)

    for (int t = 0; t < SEQ; t++) {
        // ---- h-part GEMM: 8 rows, 9-shfl multi-reduce ----
        float4 hv = ((const float4*)sH[wid])[lane];
        float acc[8];
        #pragma unroll
        for (int r = 0; r < 8; r++) {
            float4 w = sWqH[r][lane];
            float a = hv.x * w.x;
            a = fmaf(hv.y, w.y, a); a = fmaf(hv.z, w.z, a); a = fmaf(hv.w, w.w, a);
            acc[r] = a;
        }
        float y;
        {
            int t0 = lane & 1;
            float s0 = t0 ? acc[0] : acc[1], s1 = t0 ? acc[2] : acc[3];
            float s2 = t0 ? acc[4] : acc[5], s3 = t0 ? acc[6] : acc[7];
            float r0 = __shfl_xor_sync(FM, s0, 1);
            float r1 = __shfl_xor_sync(FM, s1, 1);
            float r2 = __shfl_xor_sync(FM, s2, 1);
            float r3 = __shfl_xor_sync(FM, s3, 1);
            float w0_ = (t0 ? acc[1] : acc[0]) + r0;
            float w1_ = (t0 ? acc[3] : acc[2]) + r1;
            float w2_ = (t0 ? acc[5] : acc[4]) + r2;
            float w3_ = (t0 ? acc[7] : acc[6]) + r3;
            int t1 = (lane >> 1) & 1;
            float s4 = t1 ? w0_ : w1_, s5 = t1 ? w2_ : w3_;
            float r4 = __shfl_xor_sync(FM, s4, 2);
            float r5 = __shfl_xor_sync(FM, s5, 2);
            float x0_ = (t1 ? w1_ : w0_) + r4;
            float x1_ = (t1 ? w3_ : w2_) + r5;
            int t2 = (lane >> 2) & 1;
            float s6 = t2 ? x0_ : x1_;
            float r6 = __shfl_xor_sync(FM, s6, 4);
            y = (t2 ? x1_ : x0_) + r6;       // row (lane&7) partial
            y += __shfl_xor_sync(FM, y, 8);
            y += __shfl_xor_sync(FM, y, 16); // row (lane&7) total, ALL lanes
        }
        // prefetch next qx (h-independent)
        float qxn = 0.f;
        if (t + 1 < SEQ) qxn = g_qx[((size_t)(t + 1) * BATCH + b) * NQ + v];

        // every lane: sincos of ITS row (wire v) — cs[j] lives in lane j (j<8)
        float sq, cq;
        __sincosf(y + qxc, &sq, &cq);

        // ---- Heisenberg DP (real 4-state), lane computes z[g][v] ----
        float a_ = 1.f, bb = 0.f, c_ = 0.f, d_ = 0.f;
        #pragma unroll
        for (int j = 7; j >= 0; j--) {
            float zf, xf, yf;
            if (j == 7) { zf = 0.f; xf = 1.f; yf = 0.f; }
            else {
                float cqj = __shfl_sync(FM, cq, j + 1);
                float sqj = __shfl_sync(FM, sq, j + 1);
                zf = Cg[j + 1] * cqj;
                xf = Sg[j + 1] * cqj;
                yf = -sqj;
            }
            if (j <= v) {
                float cj = cg[j], sj = sg[j];
                float na = cj * fmaf(yf, d_, bb * zf);
                float nb = cj * fmaf(xf, c_, a_);
                float nc = -sj * fmaf(xf, a_, c_);
                float nd = -sj * fmaf(-yf, bb, d_ * zf);
                a_ = na; bb = nb; c_ = nc; d_ = nd;
            }
        }
        {
            float cq0 = __shfl_sync(FM, cq, 0);
            float sq0 = __shfl_sync(FM, sq, 0);
            float E = a_;
            E = fmaf(Sg[0] * cq0, c_, E);
            E = fmaf(Cg[0] * cq0, bb, E);
            E = fmaf(-sq0, d_, E);
            zsm[wid][v][g] = E;
        }
        __syncwarp();

        // ---- epilogue: 4 hidden units per lane ----
        float4 zw[8];
        #pragma unroll
        for (int w = 0; w < NQ; w++) zw[w] = *(const float4*)&zsm[wid][w][0];

        #pragma unroll
        for (int u = 0; u < 4; u++) {
            int h = u * 32 + lane;
            u64 accfi = pk(bfv[u], biv[u]);
            u64 accgo = pk(bgv[u], bov[u]);
            #pragma unroll
            for (int w = 0; w < NQ; w++) {
                float4 ww = sWg4[w][h];
                FMA2(accfi, pk(zw[w].x, zw[w].y), pk(ww.x, ww.y), accfi);
                FMA2(accgo, pk(zw[w].z, zw[w].w), pk(ww.z, ww.w), accgo);
            }
            float accf, acci, accg, acco;
            upk(accfi, accf, acci);
            upk(accgo, accg, acco);

            float fg = __fdividef(1.f, 1.f + __expf(-accf));
            float ig = __fdividef(1.f, 1.f + __expf(-acci));
            float e2 = __expf(2.f * accg);
            float gg = __fdividef(e2 - 1.f, e2 + 1.f);
            float og = __fdividef(1.f, 1.f + __expf(-acco));

            cv[u] = fmaf(fg, cv[u], ig * gg);
            float e2c = __expf(2.f * cv[u]);
            hn[u] = og * __fdividef(e2c - 1.f, e2c + 1.f);
        }
        __syncwarp();   // all lanes done reading sH/zsm
        float* outp = out + (size_t)t * BATCH * HIDDEN + (size_t)b * HIDDEN;
        #pragma unroll
        for (int u = 0; u < 4; u++) {
            sH[wid][u * 32 + lane] = hn[u];
            outp[u * 32 + lane] = hn[u];
        }
        __syncwarp();   // h visible before next step's read
        qxc = qxn;
    }

    // ---- final hx, cx ----
    size_t base = (size_t)SEQ * BATCH * HIDDEN;
    #pragma unroll
    for (int u = 0; u < 4; u++) {
        out[base + (size_t)b * HIDDEN + u * 32 + lane] = hn[u];
        out[base + (size_t)BATCH * HIDDEN + (size_t)b * HIDDEN + u * 32 + lane] = cv[u];
    }
}

extern "C" void kernel_launch(void* const* d_in, const int* in_sizes, int n_in,
                              void* d_out, int out_size)
{
    const float* inputs = (const float*)d_in[0];
    const float* Wq     = (const float*)d_in[1];
    const float* bq     = (const float*)d_in[2];
    const float* pf     = (const float*)d_in[3];
    const float* pi_    = (const float*)d_in[4];
    const float* pg     = (const float*)d_in[5];
    const float* po     = (const float*)d_in[6];
    const float* Wf     = (const float*)d_in[7];
    const float* bf     = (const float*)d_in[8];
    const float* Wi     = (const float*)d_in[9];
    const float* bi     = (const float*)d_in[10];
    const float* Wg     = (const float*)d_in[11];
    const float* bg     = (const float*)d_in[12];
    const float* Wo     = (const float*)d_in[13];
    const float* bo     = (const float*)d_in[14];
    float* out = (float*)d_out;

    qx_pre<<<4096, 128>>>(inputs, Wq, bq);
    qlstm_all<<<BATCH / 4, 128>>>(Wq, pf, pi_, pg, po,
                                  Wf, bf, Wi, bi, Wg, bg, Wo, bo, out);
}